// round 10
// baseline (speedup 1.0000x reference)
#include <cuda_runtime.h>
#include <math.h>
#include <stdint.h>

#define BATCH 32
#define SEQ   8192
#define HID   512
#define CHUNKS 46                    // 32*46 = 1472 ~= 2 * (148 SMs * 5 blocks)
#define NTHREADS 256
#define NWARPS   8

// Deterministic per-block partials (no atomics, no fences).
__device__ float g_ctx_part[BATCH * CHUNKS * HID];   // ~3 MB scratch
__device__ float g_sum_part[BATCH * CHUNKS];

// ---------------------------------------------------------------------------
// Kernel 1: fused single-pass — streams enc_out exactly once.
// occ=5 blocks/SM (40 warps) via smem-resident states_h -> regs <= 51.
// grid = 1472 blocks ~= exactly 2 full waves at 5 blocks/SM.
// ---------------------------------------------------------------------------
__global__ __launch_bounds__(NTHREADS, 5)
void attn_main(const float* __restrict__ states_h,
               const float* __restrict__ enc_out,
               float* __restrict__ w_out)     // [BATCH*SEQ] unnormalized
{
    const int b     = blockIdx.x / CHUNKS;
    const int chunk = blockIdx.x % CHUNKS;
    const int tid   = threadIdx.x;
    const int w     = tid >> 5;
    const int lane  = tid & 31;

    const int s_begin = (chunk * SEQ) / CHUNKS;
    const int s_end   = ((chunk + 1) * SEQ) / CHUNKS;

    __shared__ float4 s_states[HID / 4];        // 2 KB: states_h[b]
    __shared__ float4 s_ctx[NWARPS][HID / 4];   // 16 KB
    __shared__ float  s_sum[NWARPS];

    // stage states_h[b] once
    if (tid < HID / 4) {
        const float4* shp = reinterpret_cast<const float4*>(states_h + b * HID);
        s_states[tid] = shp[tid];
    }
    __syncthreads();

    float4 ctx[4];
    #pragma unroll
    for (int i = 0; i < 4; i++) ctx[i] = make_float4(0.f, 0.f, 0.f, 0.f);
    float sum_e = 0.0f;

    const float* enc_b = enc_out + (size_t)b * SEQ * HID;

    #pragma unroll 2
    for (int s = s_begin + w; s < s_end; s += NWARPS) {
        const float4* row = reinterpret_cast<const float4*>(enc_b + (size_t)s * HID);
        float4 v[4];
        #pragma unroll
        for (int i = 0; i < 4; i++) v[i] = __ldcs(&row[i * 32 + lane]);

        float dot = 0.0f;
        #pragma unroll
        for (int i = 0; i < 4; i++) {
            const float4 sh = s_states[i * 32 + lane];
            dot += v[i].x * sh.x + v[i].y * sh.y
                 + v[i].z * sh.z + v[i].w * sh.w;
        }
        #pragma unroll
        for (int off = 16; off; off >>= 1)
            dot += __shfl_xor_sync(0xFFFFFFFFu, dot, off);

        const float e = __expf(dot * (1.0f / 512.0f));
        if (lane == 0) {
            w_out[(size_t)b * SEQ + s] = e;
            sum_e += e;
        }
        #pragma unroll
        for (int i = 0; i < 4; i++) {
            ctx[i].x = fmaf(e, v[i].x, ctx[i].x);
            ctx[i].y = fmaf(e, v[i].y, ctx[i].y);
            ctx[i].z = fmaf(e, v[i].z, ctx[i].z);
            ctx[i].w = fmaf(e, v[i].w, ctx[i].w);
        }
    }

    // ---- cross-warp context reduction in smem, write block partials ----
    #pragma unroll
    for (int i = 0; i < 4; i++) s_ctx[w][i * 32 + lane] = ctx[i];
    if (lane == 0) s_sum[w] = sum_e;
    __syncthreads();

    {
        const float2* sc = reinterpret_cast<const float2*>(&s_ctx[0][0]);
        const int stride2 = HID / 2;
        float2 acc = make_float2(0.f, 0.f);
        #pragma unroll
        for (int ww = 0; ww < NWARPS; ww++) {
            float2 t = sc[ww * stride2 + tid];
            acc.x += t.x; acc.y += t.y;
        }
        float2* dst = reinterpret_cast<float2*>(
            g_ctx_part + ((size_t)b * CHUNKS + chunk) * HID);
        dst[tid] = acc;
    }
    if (tid == 0) {
        float t = 0.f;
        #pragma unroll
        for (int ww = 0; ww < NWARPS; ww++) t += s_sum[ww];
        g_sum_part[b * CHUNKS + chunk] = t;
    }
}

// ---------------------------------------------------------------------------
// Kernel 2: de-serialized epilogue (R6 structure; CHUNKS<=64 supported).
// grid = BATCH*8 (w-normalize) + BATCH*2 (ctx reduce) = 320 blocks.
// ---------------------------------------------------------------------------
#define WSLICES 8    // SEQ/(NTHREADS*4)

__global__ __launch_bounds__(NTHREADS)
void attn_epilogue(float* __restrict__ ctx_out,   // [BATCH*HID]
                   float* __restrict__ w_out)     // [BATCH*SEQ]
{
    const bool is_ctx = blockIdx.x >= BATCH * WSLICES;
    const int  b      = is_ctx ? ((blockIdx.x - BATCH * WSLICES) >> 1)
                               : (blockIdx.x / WSLICES);
    const int  tid    = threadIdx.x;

    __shared__ float s_inv;

    if (!is_ctx) {
        const int slice = blockIdx.x % WSLICES;
        float4* wp = reinterpret_cast<float4*>(w_out + (size_t)b * SEQ) +
                     slice * NTHREADS;

        // issue the data load FIRST (independent of the sum reduce)
        float4 t = wp[tid];

        if (tid < 32) {
            const float* sp = g_sum_part + b * CHUNKS;
            float v = sp[tid];
            if (tid + 32 < CHUNKS) v += sp[tid + 32];
            #pragma unroll
            for (int off = 16; off; off >>= 1)
                v += __shfl_xor_sync(0xFFFFFFFFu, v, off);
            if (tid == 0) s_inv = __frcp_rn(v);
        }
        __syncthreads();
        const float inv = s_inv;

        t.x *= inv; t.y *= inv; t.z *= inv; t.w *= inv;
        wp[tid] = t;
    } else {
        const int h = ((blockIdx.x - BATCH * WSLICES) & 1) * NTHREADS + tid;

        const float* pp = g_ctx_part + (size_t)b * CHUNKS * HID + h;
        float acc = 0.0f;
        #pragma unroll
        for (int c = 0; c < CHUNKS; c++)
            acc += pp[(size_t)c * HID];

        if (tid < 32) {
            const float* sp = g_sum_part + b * CHUNKS;
            float v = sp[tid];
            if (tid + 32 < CHUNKS) v += sp[tid + 32];
            #pragma unroll
            for (int off = 16; off; off >>= 1)
                v += __shfl_xor_sync(0xFFFFFFFFu, v, off);
            if (tid == 0) s_inv = __frcp_rn(v);
        }
        __syncthreads();

        ctx_out[b * HID + h] = acc * s_inv;
    }
}

// ---------------------------------------------------------------------------
extern "C" void kernel_launch(void* const* d_in, const int* in_sizes, int n_in,
                              void* d_out, int out_size)
{
    const float* states_h = nullptr;
    const float* enc_out  = nullptr;
    for (int i = 0; i < n_in; i++) {
        if (in_sizes[i] == BATCH * HID)            states_h = (const float*)d_in[i];
        else if ((int64_t)in_sizes[i] == (int64_t)BATCH * SEQ * HID)
                                                   enc_out  = (const float*)d_in[i];
    }

    float* ctx_out = (float*)d_out;                 // [context | weights]
    float* w_out   = (float*)d_out + BATCH * HID;

    attn_main<<<BATCH * CHUNKS, NTHREADS>>>(states_h, enc_out, w_out);
    attn_epilogue<<<BATCH * WSLICES + BATCH * 2, NTHREADS>>>(ctx_out, w_out);
}

// round 11
// speedup vs baseline: 1.5134x; 1.5134x over previous
#include <cuda_runtime.h>
#include <math.h>
#include <stdint.h>

#define BATCH 32
#define SEQ   8192
#define HID   512
#define CHUNKS 37                    // 32*37 = 1184 = 2 * (148 SMs * 4 blocks) exactly
#define NTHREADS 256
#define NWARPS   8
#define STAGES   3

// Deterministic per-block partials (no atomics, no fences).
__device__ float g_ctx_part[BATCH * CHUNKS * HID];   // ~2.4 MB scratch
__device__ float g_sum_part[BATCH * CHUNKS];

// ---------------------------------------------------------------------------
// Kernel 1: fused single-pass with per-warp cp.async (LDGSTS) 3-stage ring.
// Loads complete into smem (not registers) -> sustained MLP without register
// pressure. occ=4 (32 warps/SM), regs<=64, smem=48KB (ring reused for the
// cross-warp ctx reduction after the loop).
// ---------------------------------------------------------------------------
__global__ __launch_bounds__(NTHREADS, 4)
void attn_main(const float* __restrict__ states_h,
               const float* __restrict__ enc_out,
               float* __restrict__ w_out)     // [BATCH*SEQ] unnormalized
{
    const int b     = blockIdx.x / CHUNKS;
    const int chunk = blockIdx.x % CHUNKS;
    const int tid   = threadIdx.x;
    const int w     = tid >> 5;
    const int lane  = tid & 31;

    const int s_begin = (chunk * SEQ) / CHUNKS;
    const int s_end   = ((chunk + 1) * SEQ) / CHUNKS;

    // 8 warps * 3 stages * 512 floats = 48 KB (static max). Reused after loop.
    __shared__ float s_ring[NWARPS * STAGES * HID];

    // states_h[b] in registers
    float4 sh[4];
    const float4* shp = reinterpret_cast<const float4*>(states_h + b * HID);
    #pragma unroll
    for (int i = 0; i < 4; i++) sh[i] = shp[i * 32 + lane];

    float4 ctx[4];
    #pragma unroll
    for (int i = 0; i < 4; i++) ctx[i] = make_float4(0.f, 0.f, 0.f, 0.f);
    float sum_e = 0.0f;

    const float* enc_b = enc_out + (size_t)b * SEQ * HID;
    float* ring = s_ring + w * (STAGES * HID);
    const uint32_t ring_s0 =
        (uint32_t)__cvta_generic_to_shared(ring) + (uint32_t)lane * 16u;

    // issue one row (512B/warp as 4x16B per lane) into stage st; always commit
    auto issue = [&](int s, int st) {
        if (s < s_end) {
            const char* src = (const char*)(enc_b + (size_t)s * HID) + lane * 16;
            const uint32_t dst = ring_s0 + (uint32_t)st * (HID * 4);
            #pragma unroll
            for (int j = 0; j < 4; j++)
                asm volatile("cp.async.cg.shared.global [%0], [%1], 16;"
                             :: "r"(dst + j * 512), "l"(src + j * 512) : "memory");
        }
        asm volatile("cp.async.commit_group;" ::: "memory");
    };

    int s = s_begin + w;
    issue(s, 0);
    issue(s + NWARPS, 1);
    issue(s + 2 * NWARPS, 2);

    int st = 0;
    for (; s < s_end; s += NWARPS) {
        asm volatile("cp.async.wait_group 2;" ::: "memory");

        // read ready stage (each lane reads exactly the bytes it copied)
        float4 v[4];
        const float4* vp = reinterpret_cast<const float4*>(ring + st * HID);
        #pragma unroll
        for (int j = 0; j < 4; j++) v[j] = vp[j * 32 + lane];

        // refill this stage with the row 3 ahead (lands long after the LDS)
        issue(s + STAGES * NWARPS, st);

        // compute chain on v
        float dot = 0.0f;
        #pragma unroll
        for (int j = 0; j < 4; j++) {
            dot += v[j].x * sh[j].x + v[j].y * sh[j].y
                 + v[j].z * sh[j].z + v[j].w * sh[j].w;
        }
        #pragma unroll
        for (int off = 16; off; off >>= 1)
            dot += __shfl_xor_sync(0xFFFFFFFFu, dot, off);

        const float e = __expf(dot * (1.0f / 512.0f));
        if (lane == 0) {
            w_out[(size_t)b * SEQ + s] = e;
            sum_e += e;
        }
        #pragma unroll
        for (int j = 0; j < 4; j++) {
            ctx[j].x = fmaf(e, v[j].x, ctx[j].x);
            ctx[j].y = fmaf(e, v[j].y, ctx[j].y);
            ctx[j].z = fmaf(e, v[j].z, ctx[j].z);
            ctx[j].w = fmaf(e, v[j].w, ctx[j].w);
        }

        st = (st == STAGES - 1) ? 0 : st + 1;
    }
    asm volatile("cp.async.wait_group 0;" ::: "memory");
    __syncthreads();

    // ---- reuse ring smem for cross-warp ctx reduction ----
    {
        float4* cw = reinterpret_cast<float4*>(s_ring + w * HID);
        #pragma unroll
        for (int i = 0; i < 4; i++) cw[i * 32 + lane] = ctx[i];
        if (lane == 0) s_ring[NWARPS * HID + w] = sum_e;   // sums at +16KB
    }
    __syncthreads();

    {
        const float2* sc = reinterpret_cast<const float2*>(s_ring);
        const int stride2 = HID / 2;
        float2 acc = make_float2(0.f, 0.f);
        #pragma unroll
        for (int ww = 0; ww < NWARPS; ww++) {
            float2 t = sc[ww * stride2 + tid];
            acc.x += t.x; acc.y += t.y;
        }
        float2* dst = reinterpret_cast<float2*>(
            g_ctx_part + ((size_t)b * CHUNKS + chunk) * HID);
        dst[tid] = acc;
    }
    if (tid == 0) {
        float t = 0.f;
        #pragma unroll
        for (int ww = 0; ww < NWARPS; ww++) t += s_ring[NWARPS * HID + ww];
        g_sum_part[b * CHUNKS + chunk] = t;
    }
}

// ---------------------------------------------------------------------------
// Kernel 2: de-serialized epilogue (R6 best version).
// ---------------------------------------------------------------------------
#define WSLICES 8    // SEQ/(NTHREADS*4)

__global__ __launch_bounds__(NTHREADS)
void attn_epilogue(float* __restrict__ ctx_out,   // [BATCH*HID]
                   float* __restrict__ w_out)     // [BATCH*SEQ]
{
    const bool is_ctx = blockIdx.x >= BATCH * WSLICES;
    const int  b      = is_ctx ? ((blockIdx.x - BATCH * WSLICES) >> 1)
                               : (blockIdx.x / WSLICES);
    const int  tid    = threadIdx.x;

    __shared__ float s_inv;

    if (!is_ctx) {
        const int slice = blockIdx.x % WSLICES;
        float4* wp = reinterpret_cast<float4*>(w_out + (size_t)b * SEQ) +
                     slice * NTHREADS;

        float4 t = wp[tid];                      // load before sum resolves

        if (tid < 32) {
            const float* sp = g_sum_part + b * CHUNKS;
            float v = sp[tid];
            if (tid + 32 < CHUNKS) v += sp[tid + 32];
            #pragma unroll
            for (int off = 16; off; off >>= 1)
                v += __shfl_xor_sync(0xFFFFFFFFu, v, off);
            if (tid == 0) s_inv = __frcp_rn(v);
        }
        __syncthreads();
        const float inv = s_inv;

        t.x *= inv; t.y *= inv; t.z *= inv; t.w *= inv;
        wp[tid] = t;
    } else {
        const int h = ((blockIdx.x - BATCH * WSLICES) & 1) * NTHREADS + tid;

        const float* pp = g_ctx_part + (size_t)b * CHUNKS * HID + h;
        float acc = 0.0f;
        #pragma unroll
        for (int c = 0; c < CHUNKS; c++)
            acc += pp[(size_t)c * HID];

        if (tid < 32) {
            const float* sp = g_sum_part + b * CHUNKS;
            float v = sp[tid];
            if (tid + 32 < CHUNKS) v += sp[tid + 32];
            #pragma unroll
            for (int off = 16; off; off >>= 1)
                v += __shfl_xor_sync(0xFFFFFFFFu, v, off);
            if (tid == 0) s_inv = __frcp_rn(v);
        }
        __syncthreads();

        ctx_out[b * HID + h] = acc * s_inv;
    }
}

// ---------------------------------------------------------------------------
extern "C" void kernel_launch(void* const* d_in, const int* in_sizes, int n_in,
                              void* d_out, int out_size)
{
    const float* states_h = nullptr;
    const float* enc_out  = nullptr;
    for (int i = 0; i < n_in; i++) {
        if (in_sizes[i] == BATCH * HID)            states_h = (const float*)d_in[i];
        else if ((int64_t)in_sizes[i] == (int64_t)BATCH * SEQ * HID)
                                                   enc_out  = (const float*)d_in[i];
    }

    float* ctx_out = (float*)d_out;                 // [context | weights]
    float* w_out   = (float*)d_out + BATCH * HID;

    attn_main<<<BATCH * CHUNKS, NTHREADS>>>(states_h, enc_out, w_out);
    attn_epilogue<<<BATCH * WSLICES + BATCH * 2, NTHREADS>>>(ctx_out, w_out);
}

// round 12
// speedup vs baseline: 1.5470x; 1.0222x over previous
#include <cuda_runtime.h>
#include <math.h>
#include <stdint.h>

#define BATCH 32
#define SEQ   8192
#define HID   512
#define CHUNKS 74                    // 32*74 = 2368 = 2 * (148 SMs * 8 blocks) exactly
#define NTHREADS 128
#define NWARPS   4

// Deterministic per-block partials (no atomics, no fences).
__device__ float g_ctx_part[BATCH * CHUNKS * HID];   // ~4.9 MB scratch
__device__ float g_sum_part[BATCH * CHUNKS];

// ---------------------------------------------------------------------------
// Kernel 1: fused single-pass — streams enc_out exactly once.
// 128-thread blocks, 8 blocks/SM (same 32 warps/SM as before) -> halved
// per-CTA tail, finer wave-2 backfill. grid = 2368 = exactly 2 full waves.
// Loop body identical to the measured-best R4 version.
// ---------------------------------------------------------------------------
__global__ __launch_bounds__(NTHREADS, 8)
void attn_main(const float* __restrict__ states_h,
               const float* __restrict__ enc_out,
               float* __restrict__ w_out)     // [BATCH*SEQ] unnormalized
{
    const int b     = blockIdx.x / CHUNKS;
    const int chunk = blockIdx.x % CHUNKS;
    const int tid   = threadIdx.x;
    const int w     = tid >> 5;
    const int lane  = tid & 31;

    const int s_begin = (chunk * SEQ) / CHUNKS;   // ~110-111 rows per chunk
    const int s_end   = ((chunk + 1) * SEQ) / CHUNKS;

    // states_h[b] in registers: lane covers h = i*128 + lane*4 + {0..3}
    float4 sh[4];
    const float4* shp = reinterpret_cast<const float4*>(states_h + b * HID);
    #pragma unroll
    for (int i = 0; i < 4; i++) sh[i] = shp[i * 32 + lane];

    float4 ctx[4];
    #pragma unroll
    for (int i = 0; i < 4; i++) ctx[i] = make_float4(0.f, 0.f, 0.f, 0.f);
    float sum_e = 0.0f;

    const float* enc_b = enc_out + (size_t)b * SEQ * HID;

    #pragma unroll 2
    for (int s = s_begin + w; s < s_end; s += NWARPS) {
        const float4* row = reinterpret_cast<const float4*>(enc_b + (size_t)s * HID);
        float4 v[4];
        #pragma unroll
        for (int i = 0; i < 4; i++) v[i] = __ldcs(&row[i * 32 + lane]);

        float dot = 0.0f;
        #pragma unroll
        for (int i = 0; i < 4; i++) {
            dot += v[i].x * sh[i].x + v[i].y * sh[i].y
                 + v[i].z * sh[i].z + v[i].w * sh[i].w;
        }
        #pragma unroll
        for (int off = 16; off; off >>= 1)
            dot += __shfl_xor_sync(0xFFFFFFFFu, dot, off);

        const float e = __expf(dot * (1.0f / 512.0f));
        if (lane == 0) {
            w_out[(size_t)b * SEQ + s] = e;
            sum_e += e;
        }
        #pragma unroll
        for (int i = 0; i < 4; i++) {
            ctx[i].x = fmaf(e, v[i].x, ctx[i].x);
            ctx[i].y = fmaf(e, v[i].y, ctx[i].y);
            ctx[i].z = fmaf(e, v[i].z, ctx[i].z);
            ctx[i].w = fmaf(e, v[i].w, ctx[i].w);
        }
    }

    // ---- cross-warp context reduction in smem, write block partials ----
    __shared__ float4 s_ctx[NWARPS][HID / 4];   // 8 KB
    __shared__ float  s_sum[NWARPS];
    #pragma unroll
    for (int i = 0; i < 4; i++) s_ctx[w][i * 32 + lane] = ctx[i];
    if (lane == 0) s_sum[w] = sum_e;
    __syncthreads();

    // 128 threads: each covers float2 positions tid and tid+128 (512 floats)
    {
        const float2* sc = reinterpret_cast<const float2*>(&s_ctx[0][0]);
        const int stride2 = HID / 2;                  // 256 float2 per warp slice
        float2* dst = reinterpret_cast<float2*>(
            g_ctx_part + ((size_t)b * CHUNKS + chunk) * HID);
        #pragma unroll
        for (int p = 0; p < 2; p++) {
            const int idx = p * NTHREADS + tid;
            float2 acc = make_float2(0.f, 0.f);
            #pragma unroll
            for (int ww = 0; ww < NWARPS; ww++) {
                float2 t = sc[ww * stride2 + idx];
                acc.x += t.x; acc.y += t.y;
            }
            dst[idx] = acc;
        }
    }
    if (tid == 0) {
        float t = 0.f;
        #pragma unroll
        for (int ww = 0; ww < NWARPS; ww++) t += s_sum[ww];
        g_sum_part[b * CHUNKS + chunk] = t;
    }
}

// ---------------------------------------------------------------------------
// Kernel 2: de-serialized epilogue (R6 structure, CHUNKS=74).
// grid = BATCH*8 (w-normalize, 256 thr) + BATCH*2 (ctx reduce) = 320 blocks.
// ---------------------------------------------------------------------------
#define EPI_THREADS 256
#define WSLICES 8    // SEQ/(EPI_THREADS*4)

__device__ __forceinline__ float batch_inv_sum(int b, int tid) {
    // reduce 74 partials with warp 0; callers read the returned value from
    // lane 0 via shared broadcast (done by caller)
    const float* sp = g_sum_part + b * CHUNKS;
    float v = sp[tid] + sp[tid + 32];
    if (tid + 64 < CHUNKS) v += sp[tid + 64];
    #pragma unroll
    for (int off = 16; off; off >>= 1)
        v += __shfl_xor_sync(0xFFFFFFFFu, v, off);
    return v;
}

__global__ __launch_bounds__(EPI_THREADS)
void attn_epilogue(float* __restrict__ ctx_out,   // [BATCH*HID]
                   float* __restrict__ w_out)     // [BATCH*SEQ]
{
    const bool is_ctx = blockIdx.x >= BATCH * WSLICES;
    const int  b      = is_ctx ? ((blockIdx.x - BATCH * WSLICES) >> 1)
                               : (blockIdx.x / WSLICES);
    const int  tid    = threadIdx.x;

    __shared__ float s_inv;

    if (!is_ctx) {
        const int slice = blockIdx.x % WSLICES;
        float4* wp = reinterpret_cast<float4*>(w_out + (size_t)b * SEQ) +
                     slice * EPI_THREADS;

        // issue the data load FIRST (independent of the sum reduce)
        float4 t = wp[tid];

        if (tid < 32) {
            float v = batch_inv_sum(b, tid);
            if (tid == 0) s_inv = __frcp_rn(v);
        }
        __syncthreads();
        const float inv = s_inv;

        t.x *= inv; t.y *= inv; t.z *= inv; t.w *= inv;
        wp[tid] = t;
    } else {
        const int h = ((blockIdx.x - BATCH * WSLICES) & 1) * EPI_THREADS + tid;

        const float* pp = g_ctx_part + (size_t)b * CHUNKS * HID + h;
        float acc = 0.0f;
        #pragma unroll
        for (int c = 0; c < CHUNKS; c++)
            acc += pp[(size_t)c * HID];

        if (tid < 32) {
            float v = batch_inv_sum(b, tid);
            if (tid == 0) s_inv = __frcp_rn(v);
        }
        __syncthreads();

        ctx_out[b * HID + h] = acc * s_inv;
    }
}

// ---------------------------------------------------------------------------
extern "C" void kernel_launch(void* const* d_in, const int* in_sizes, int n_in,
                              void* d_out, int out_size)
{
    const float* states_h = nullptr;
    const float* enc_out  = nullptr;
    for (int i = 0; i < n_in; i++) {
        if (in_sizes[i] == BATCH * HID)            states_h = (const float*)d_in[i];
        else if ((int64_t)in_sizes[i] == (int64_t)BATCH * SEQ * HID)
                                                   enc_out  = (const float*)d_in[i];
    }

    float* ctx_out = (float*)d_out;                 // [context | weights]
    float* w_out   = (float*)d_out + BATCH * HID;

    attn_main<<<BATCH * CHUNKS, NTHREADS>>>(states_h, enc_out, w_out);
    attn_epilogue<<<BATCH * WSLICES + BATCH * 2, EPI_THREADS>>>(ctx_out, w_out);
}

// round 13
// speedup vs baseline: 1.5851x; 1.0246x over previous
#include <cuda_runtime.h>
#include <math.h>
#include <stdint.h>

#define BATCH 32
#define SEQ   8192
#define HID   512
#define CHUNKS 37                    // 32*37 = 1184 = 2 * (148 SMs * 4 blocks) exactly
#define NTHREADS 256
#define NWARPS   8

// Deterministic per-block partials (no atomics, no fences).
__device__ float g_ctx_part[BATCH * CHUNKS * HID];   // ~2.4 MB scratch
__device__ float g_sum_part[BATCH * CHUNKS];

// ---------------------------------------------------------------------------
// Kernel 1: fused single-pass — streams enc_out exactly once.
// grid = 1184 blocks = exactly 2 full waves at 4 blocks/SM (RF-limit point:
// 64 regs x 256 thr x 4 blocks = full register file). Measured best: ~77us,
// 6.5 TB/s effective on enc_out. (R4 verbatim.)
// ---------------------------------------------------------------------------
__global__ __launch_bounds__(NTHREADS, 4)
void attn_main(const float* __restrict__ states_h,
               const float* __restrict__ enc_out,
               float* __restrict__ w_out)     // [BATCH*SEQ] unnormalized
{
    const int b     = blockIdx.x / CHUNKS;
    const int chunk = blockIdx.x % CHUNKS;
    const int tid   = threadIdx.x;
    const int w     = tid >> 5;
    const int lane  = tid & 31;

    const int s_begin = (chunk * SEQ) / CHUNKS;
    const int s_end   = ((chunk + 1) * SEQ) / CHUNKS;

    // states_h[b] in registers: lane covers h = i*128 + lane*4 + {0..3}
    float4 sh[4];
    const float4* shp = reinterpret_cast<const float4*>(states_h + b * HID);
    #pragma unroll
    for (int i = 0; i < 4; i++) sh[i] = shp[i * 32 + lane];

    float4 ctx[4];
    #pragma unroll
    for (int i = 0; i < 4; i++) ctx[i] = make_float4(0.f, 0.f, 0.f, 0.f);
    float sum_e = 0.0f;

    const float* enc_b = enc_out + (size_t)b * SEQ * HID;

    #pragma unroll 2
    for (int s = s_begin + w; s < s_end; s += NWARPS) {
        const float4* row = reinterpret_cast<const float4*>(enc_b + (size_t)s * HID);
        float4 v[4];
        #pragma unroll
        for (int i = 0; i < 4; i++) v[i] = __ldcs(&row[i * 32 + lane]);

        float dot = 0.0f;
        #pragma unroll
        for (int i = 0; i < 4; i++) {
            dot += v[i].x * sh[i].x + v[i].y * sh[i].y
                 + v[i].z * sh[i].z + v[i].w * sh[i].w;
        }
        #pragma unroll
        for (int off = 16; off; off >>= 1)
            dot += __shfl_xor_sync(0xFFFFFFFFu, dot, off);

        const float e = __expf(dot * (1.0f / 512.0f));
        if (lane == 0) {
            w_out[(size_t)b * SEQ + s] = e;
            sum_e += e;
        }
        #pragma unroll
        for (int i = 0; i < 4; i++) {
            ctx[i].x = fmaf(e, v[i].x, ctx[i].x);
            ctx[i].y = fmaf(e, v[i].y, ctx[i].y);
            ctx[i].z = fmaf(e, v[i].z, ctx[i].z);
            ctx[i].w = fmaf(e, v[i].w, ctx[i].w);
        }
    }

    // ---- cross-warp context reduction in smem, write block partials ----
    __shared__ float4 s_ctx[NWARPS][HID / 4];   // 16 KB
    __shared__ float  s_sum[NWARPS];
    #pragma unroll
    for (int i = 0; i < 4; i++) s_ctx[w][i * 32 + lane] = ctx[i];
    if (lane == 0) s_sum[w] = sum_e;
    __syncthreads();

    {
        const float2* sc = reinterpret_cast<const float2*>(&s_ctx[0][0]);
        const int stride2 = HID / 2;
        float2 acc = make_float2(0.f, 0.f);
        #pragma unroll
        for (int ww = 0; ww < NWARPS; ww++) {
            float2 t = sc[ww * stride2 + tid];
            acc.x += t.x; acc.y += t.y;
        }
        float2* dst = reinterpret_cast<float2*>(
            g_ctx_part + ((size_t)b * CHUNKS + chunk) * HID);
        dst[tid] = acc;
    }
    if (tid == 0) {
        float t = 0.f;
        #pragma unroll
        for (int ww = 0; ww < NWARPS; ww++) t += s_sum[ww];
        g_sum_part[b * CHUNKS + chunk] = t;
    }
}

// ---------------------------------------------------------------------------
// Kernel 2: de-serialized epilogue (measured 5.6us).
// Long-pole ctx-reduce blocks are FIRST in the grid (bid 0..63) so they start
// in wave-1 scheduling order; w-slice blocks (1 float4/thread) fill behind.
// Data loads issue BEFORE the inv-sum resolves (independent) -> one DRAM trip.
// ---------------------------------------------------------------------------
#define WSLICES 8    // SEQ/(NTHREADS*4)
#define CTXBLKS (BATCH * 2)

__global__ __launch_bounds__(NTHREADS)
void attn_epilogue(float* __restrict__ ctx_out,   // [BATCH*HID]
                   float* __restrict__ w_out)     // [BATCH*SEQ]
{
    const bool is_ctx = blockIdx.x < CTXBLKS;
    const int  b      = is_ctx ? (blockIdx.x >> 1)
                               : ((blockIdx.x - CTXBLKS) / WSLICES);
    const int  tid    = threadIdx.x;

    __shared__ float s_inv;

    if (is_ctx) {
        // ctx reduce: 2 blocks per batch, one h per thread; 37 independent
        // partial loads accumulate while warp 0 reduces the sums in parallel.
        const int h = (blockIdx.x & 1) * NTHREADS + tid;

        const float* pp = g_ctx_part + (size_t)b * CHUNKS * HID + h;
        float acc = 0.0f;
        #pragma unroll
        for (int c = 0; c < CHUNKS; c++)
            acc += pp[(size_t)c * HID];

        if (tid < 32) {
            const float* sp = g_sum_part + b * CHUNKS;
            float v = sp[tid];
            if (tid + 32 < CHUNKS) v += sp[tid + 32];
            #pragma unroll
            for (int off = 16; off; off >>= 1)
                v += __shfl_xor_sync(0xFFFFFFFFu, v, off);
            if (tid == 0) s_inv = __frcp_rn(v);
        }
        __syncthreads();

        ctx_out[b * HID + h] = acc * s_inv;
    } else {
        const int slice = (blockIdx.x - CTXBLKS) % WSLICES;
        float4* wp = reinterpret_cast<float4*>(w_out + (size_t)b * SEQ) +
                     slice * NTHREADS;

        // issue the data load FIRST (independent of the sum reduce)
        float4 t = wp[tid];

        if (tid < 32) {
            const float* sp = g_sum_part + b * CHUNKS;
            float v = sp[tid];
            if (tid + 32 < CHUNKS) v += sp[tid + 32];
            #pragma unroll
            for (int off = 16; off; off >>= 1)
                v += __shfl_xor_sync(0xFFFFFFFFu, v, off);
            if (tid == 0) s_inv = __frcp_rn(v);
        }
        __syncthreads();
        const float inv = s_inv;

        t.x *= inv; t.y *= inv; t.z *= inv; t.w *= inv;
        wp[tid] = t;
    }
}

// ---------------------------------------------------------------------------
extern "C" void kernel_launch(void* const* d_in, const int* in_sizes, int n_in,
                              void* d_out, int out_size)
{
    const float* states_h = nullptr;
    const float* enc_out  = nullptr;
    for (int i = 0; i < n_in; i++) {
        if (in_sizes[i] == BATCH * HID)            states_h = (const float*)d_in[i];
        else if ((int64_t)in_sizes[i] == (int64_t)BATCH * SEQ * HID)
                                                   enc_out  = (const float*)d_in[i];
    }

    float* ctx_out = (float*)d_out;                 // [context | weights]
    float* w_out   = (float*)d_out + BATCH * HID;

    attn_main<<<BATCH * CHUNKS, NTHREADS>>>(states_h, enc_out, w_out);
    attn_epilogue<<<CTXBLKS + BATCH * WSLICES, NTHREADS>>>(ctx_out, w_out);
}

// round 14
// speedup vs baseline: 1.6238x; 1.0245x over previous
#include <cuda_runtime.h>
#include <math.h>
#include <stdint.h>

#define BATCH 32
#define SEQ   8192
#define HID   512
#define CHUNKS 37                    // 32*37 = 1184 = 2 * (148 SMs * 4 blocks) exactly
#define NTHREADS 256
#define NWARPS   8

// Deterministic per-block partials (no atomics, no fences).
__device__ float g_ctx_part[BATCH * CHUNKS * HID];   // ~2.4 MB scratch
__device__ float g_sum_part[BATCH * CHUNKS];

// ---------------------------------------------------------------------------
// Kernel 1: fused single-pass — streams enc_out exactly once.
// grid = 1184 blocks = exactly 2 full waves at 4 blocks/SM (RF-limit point:
// 64 regs x 256 thr x 4 blocks = full register file). Measured ~78.8us,
// ~6.5 TB/s effective on enc_out — at the streaming ceiling.
// ---------------------------------------------------------------------------
__global__ __launch_bounds__(NTHREADS, 4)
void attn_main(const float* __restrict__ states_h,
               const float* __restrict__ enc_out,
               float* __restrict__ w_out)     // [BATCH*SEQ] unnormalized
{
    const int b     = blockIdx.x / CHUNKS;
    const int chunk = blockIdx.x % CHUNKS;
    const int tid   = threadIdx.x;
    const int w     = tid >> 5;
    const int lane  = tid & 31;

    const int s_begin = (chunk * SEQ) / CHUNKS;
    const int s_end   = ((chunk + 1) * SEQ) / CHUNKS;

    // states_h[b] in registers: lane covers h = i*128 + lane*4 + {0..3}
    float4 sh[4];
    const float4* shp = reinterpret_cast<const float4*>(states_h + b * HID);
    #pragma unroll
    for (int i = 0; i < 4; i++) sh[i] = shp[i * 32 + lane];

    float4 ctx[4];
    #pragma unroll
    for (int i = 0; i < 4; i++) ctx[i] = make_float4(0.f, 0.f, 0.f, 0.f);
    float sum_e = 0.0f;

    const float* enc_b = enc_out + (size_t)b * SEQ * HID;

    #pragma unroll 2
    for (int s = s_begin + w; s < s_end; s += NWARPS) {
        const float4* row = reinterpret_cast<const float4*>(enc_b + (size_t)s * HID);
        float4 v[4];
        #pragma unroll
        for (int i = 0; i < 4; i++) v[i] = __ldcs(&row[i * 32 + lane]);

        float dot = 0.0f;
        #pragma unroll
        for (int i = 0; i < 4; i++) {
            dot += v[i].x * sh[i].x + v[i].y * sh[i].y
                 + v[i].z * sh[i].z + v[i].w * sh[i].w;
        }
        #pragma unroll
        for (int off = 16; off; off >>= 1)
            dot += __shfl_xor_sync(0xFFFFFFFFu, dot, off);

        const float e = __expf(dot * (1.0f / 512.0f));
        if (lane == 0) {
            w_out[(size_t)b * SEQ + s] = e;
            sum_e += e;
        }
        #pragma unroll
        for (int i = 0; i < 4; i++) {
            ctx[i].x = fmaf(e, v[i].x, ctx[i].x);
            ctx[i].y = fmaf(e, v[i].y, ctx[i].y);
            ctx[i].z = fmaf(e, v[i].z, ctx[i].z);
            ctx[i].w = fmaf(e, v[i].w, ctx[i].w);
        }
    }

    // ---- cross-warp context reduction in smem, write block partials ----
    __shared__ float4 s_ctx[NWARPS][HID / 4];   // 16 KB
    __shared__ float  s_sum[NWARPS];
    #pragma unroll
    for (int i = 0; i < 4; i++) s_ctx[w][i * 32 + lane] = ctx[i];
    if (lane == 0) s_sum[w] = sum_e;
    __syncthreads();

    {
        const float2* sc = reinterpret_cast<const float2*>(&s_ctx[0][0]);
        const int stride2 = HID / 2;
        float2 acc = make_float2(0.f, 0.f);
        #pragma unroll
        for (int ww = 0; ww < NWARPS; ww++) {
            float2 t = sc[ww * stride2 + tid];
            acc.x += t.x; acc.y += t.y;
        }
        float2* dst = reinterpret_cast<float2*>(
            g_ctx_part + ((size_t)b * CHUNKS + chunk) * HID);
        dst[tid] = acc;
    }
    if (tid == 0) {
        float t = 0.f;
        #pragma unroll
        for (int ww = 0; ww < NWARPS; ww++) t += s_sum[ww];
        g_sum_part[b * CHUNKS + chunk] = t;
    }
}

// ---------------------------------------------------------------------------
// Kernel 2: de-serialized epilogue.
// Long-pole ctx-reduce blocks first (bid 0..63); w-blocks cover 2 float4 per
// thread (4 blocks/batch) -> 192 total blocks. All data loads issue BEFORE
// the inv-sum resolves -> one DRAM/L2 round trip.
// ---------------------------------------------------------------------------
#define WSLICES 4    // SEQ/(NTHREADS*8): 4 w-blocks per batch, 2 float4/thread
#define CTXBLKS (BATCH * 2)

__global__ __launch_bounds__(NTHREADS)
void attn_epilogue(float* __restrict__ ctx_out,   // [BATCH*HID]
                   float* __restrict__ w_out)     // [BATCH*SEQ]
{
    const bool is_ctx = blockIdx.x < CTXBLKS;
    const int  b      = is_ctx ? (blockIdx.x >> 1)
                               : ((blockIdx.x - CTXBLKS) / WSLICES);
    const int  tid    = threadIdx.x;

    __shared__ float s_inv;

    if (is_ctx) {
        // ctx reduce: 2 blocks per batch, one h per thread; 37 independent
        // partial loads accumulate while warp 0 reduces the sums in parallel.
        const int h = (blockIdx.x & 1) * NTHREADS + tid;

        const float* pp = g_ctx_part + (size_t)b * CHUNKS * HID + h;
        float acc = 0.0f;
        #pragma unroll
        for (int c = 0; c < CHUNKS; c++)
            acc += pp[(size_t)c * HID];

        if (tid < 32) {
            const float* sp = g_sum_part + b * CHUNKS;
            float v = sp[tid];
            if (tid + 32 < CHUNKS) v += sp[tid + 32];
            #pragma unroll
            for (int off = 16; off; off >>= 1)
                v += __shfl_xor_sync(0xFFFFFFFFu, v, off);
            if (tid == 0) s_inv = __frcp_rn(v);
        }
        __syncthreads();

        ctx_out[b * HID + h] = acc * s_inv;
    } else {
        const int slice = (blockIdx.x - CTXBLKS) % WSLICES;
        float4* wp = reinterpret_cast<float4*>(w_out + (size_t)b * SEQ) +
                     (size_t)slice * NTHREADS * 2;

        // issue BOTH data loads first (independent of the sum reduce)
        float4 t0 = wp[tid];
        float4 t1 = wp[tid + NTHREADS];

        if (tid < 32) {
            const float* sp = g_sum_part + b * CHUNKS;
            float v = sp[tid];
            if (tid + 32 < CHUNKS) v += sp[tid + 32];
            #pragma unroll
            for (int off = 16; off; off >>= 1)
                v += __shfl_xor_sync(0xFFFFFFFFu, v, off);
            if (tid == 0) s_inv = __frcp_rn(v);
        }
        __syncthreads();
        const float inv = s_inv;

        t0.x *= inv; t0.y *= inv; t0.z *= inv; t0.w *= inv;
        t1.x *= inv; t1.y *= inv; t1.z *= inv; t1.w *= inv;
        wp[tid]            = t0;
        wp[tid + NTHREADS] = t1;
    }
}

// ---------------------------------------------------------------------------
extern "C" void kernel_launch(void* const* d_in, const int* in_sizes, int n_in,
                              void* d_out, int out_size)
{
    const float* states_h = nullptr;
    const float* enc_out  = nullptr;
    for (int i = 0; i < n_in; i++) {
        if (in_sizes[i] == BATCH * HID)            states_h = (const float*)d_in[i];
        else if ((int64_t)in_sizes[i] == (int64_t)BATCH * SEQ * HID)
                                                   enc_out  = (const float*)d_in[i];
    }

    float* ctx_out = (float*)d_out;                 // [context | weights]
    float* w_out   = (float*)d_out + BATCH * HID;

    attn_main<<<BATCH * CHUNKS, NTHREADS>>>(states_h, enc_out, w_out);
    attn_epilogue<<<CTXBLKS + BATCH * WSLICES, NTHREADS>>>(ctx_out, w_out);
}